// round 4
// baseline (speedup 1.0000x reference)
#include <cuda_runtime.h>
#include <math.h>

// Problem dims (fixed by setup_inputs)
#define BDIM 2
#define NTOT 1024
#define PLEN 768
#define LLEN 256
#define KDIM 128
#define HDIM 32

constexpr int TM    = 64;
constexpr int PITCH = 132;   // float pitch of G/V1/V2 rows: 528B, 16B-aligned, 8-lane bank wrap
constexpr int NT_LL = BDIM * LLEN * (LLEN / TM);   // 2048
constexpr int NT_LP = BDIM * PLEN * (LLEN / TM);   // 6144
constexpr int NTILES = NT_LL + NT_LP;              // 8192

// shared memory layout (float offsets)
// ow1 k-pair interleaved:  OW1[kp][c] pairs -> sm[OFF_OW1 + kp*256 + 2c + {0,1}]
// ow2/vw2 k-pair interleaved: sm[OFF + kp*64 + 2h + {0,1}]
constexpr int OFF_OW1  = 0;
constexpr int OFF_OW2  = OFF_OW1 + 64 * 256;       // 16384
constexpr int OFF_VW2  = OFF_OW2 + 64 * 64;        // 20480
constexpr int OFF_VW1  = OFF_VW2 + 64 * 64;        // 24576
constexpr int OFF_VB1  = OFF_VW1 + 3 * KDIM;       // 24960
constexpr int OFF_OB1  = OFF_VB1 + KDIM;           // 25088
constexpr int OFF_MEAN = OFF_OB1 + KDIM;           // 25216
constexpr int OFF_ISTD = OFF_MEAN + KDIM;          // 25344
constexpr int OFF_COEF = OFF_ISTD + KDIM;          // 25472
constexpr int OFF_B2   = OFF_COEF + KDIM;          // 25600
constexpr int OFF_FLAG = OFF_B2 + HDIM;            // 25632 (vb1-all-zero flag)
constexpr int OFF_X0   = OFF_FLAG + 4;             // 25636
constexpr int OFF_DLM  = OFF_X0 + TM;              // 25700
constexpr int OFF_G    = OFF_DLM + TM * 3;         // 25892 -> pad to 16B: use 25892? need %4==0
// 25892 % 4 == 0 ✓ (byte 103568 % 16 == 0 ✓)
constexpr int OFF_V1   = OFF_G + TM * PITCH;       // 34340
constexpr int OFF_V2   = OFF_V1 + TM * PITCH;      // 42788
constexpr int SCPITCH  = 68;                       // scratch row pitch (floats)
constexpr int OFF_SCR  = OFF_V2 + TM * PITCH;      // 51236
constexpr int SMEM_FLOATS = OFF_SCR + TM * SCPITCH; // 55588
constexpr int SMEM_BYTES  = SMEM_FLOATS * 4;        // 222352

typedef unsigned long long ull;

__device__ __forceinline__ void lds_b128(ull &a, ull &b, unsigned addr) {
    asm volatile("ld.shared.v2.b64 {%0,%1},[%2];" : "=l"(a), "=l"(b) : "r"(addr));
}
__device__ __forceinline__ ull ffma2(ull a, ull b, ull c) {
    ull d; asm("fma.rn.f32x2 %0,%1,%2,%3;" : "=l"(d) : "l"(a), "l"(b), "l"(c)); return d;
}
__device__ __forceinline__ float2 u2f2(ull v) {
    float2 f; asm("mov.b64 {%0,%1},%2;" : "=f"(f.x), "=f"(f.y) : "l"(v)); return f;
}
__device__ __forceinline__ float gelu_exact(float x) {
    return 0.5f * x * (1.0f + erff(x * 0.70710678118654752f));
}

// Zero-fill the protein-protein quadrant: out[b,h,i>=L,j>=L]
__global__ void zero_pp_kernel(float* __restrict__ out) {
    const int q = PLEN / 4;
    size_t idx = (size_t)blockIdx.x * blockDim.x + threadIdx.x;
    size_t total = (size_t)BDIM * HDIM * PLEN * q;
    if (idx >= total) return;
    int jq = (int)(idx % q);
    size_t r = idx / q;
    int ip = (int)(r % PLEN);
    size_t bh = r / PLEN;
    size_t addr = (bh * NTOT + (LLEN + ip)) * NTOT + LLEN + 4 * jq;
    *reinterpret_cast<float4*>(out + addr) = make_float4(0.f, 0.f, 0.f, 0.f);
}

__global__ __launch_bounds__(512, 1)
void fused_distbias_kernel(
    const float* __restrict__ pos,
    const int*   __restrict__ etype,
    const float* __restrict__ mw,
    const float* __restrict__ bw,
    const float* __restrict__ means,
    const float* __restrict__ stds,
    const float* __restrict__ ow1,
    const float* __restrict__ ob1,
    const float* __restrict__ ow2,
    const float* __restrict__ ob2,
    const float* __restrict__ vw1,
    const float* __restrict__ vb1,
    const float* __restrict__ vw2,
    const float* __restrict__ vb2,
    float* __restrict__ out)
{
    extern __shared__ float sm[];
    const int tid = threadIdx.x;
    const unsigned smb = (unsigned)__cvta_generic_to_shared(sm);

    // ---- Stage weights (k-pair interleaved), once per block ----
    for (int i = tid; i < 64 * 128; i += 512) {
        int kp = i >> 7, c = i & 127;
        sm[OFF_OW1 + kp * 256 + 2 * c]     = ow1[(2 * kp) * KDIM + c];
        sm[OFF_OW1 + kp * 256 + 2 * c + 1] = ow1[(2 * kp + 1) * KDIM + c];
    }
    for (int i = tid; i < 64 * 32; i += 512) {
        int kp = i >> 5, h = i & 31;
        sm[OFF_OW2 + kp * 64 + 2 * h]     = ow2[(2 * kp) * HDIM + h];
        sm[OFF_OW2 + kp * 64 + 2 * h + 1] = ow2[(2 * kp + 1) * HDIM + h];
        sm[OFF_VW2 + kp * 64 + 2 * h]     = vw2[(2 * kp) * HDIM + h];
        sm[OFF_VW2 + kp * 64 + 2 * h + 1] = vw2[(2 * kp + 1) * HDIM + h];
    }
    for (int i = tid; i < 3 * KDIM; i += 512) sm[OFF_VW1 + i] = vw1[i];
    for (int i = tid; i < KDIM; i += 512) {
        sm[OFF_VB1 + i] = vb1[i];
        sm[OFF_OB1 + i] = ob1[i];
        float s  = fabsf(stds[i]) + 1e-5f;
        float is = 1.0f / s;
        sm[OFF_MEAN + i] = means[i];
        sm[OFF_ISTD + i] = is;
        sm[OFF_COEF + i] = is * (1.0f / sqrtf(2.0f * 3.14159f));
    }
    if (tid < HDIM) sm[OFF_B2 + tid] = ob2[tid] + vb2[tid];
    if (tid == 0) {
        int f = 1;
        for (int k = 0; k < KDIM; k++) if (vb1[k] != 0.0f) { f = 0; break; }
        *reinterpret_cast<int*>(sm + OFF_FLAG) = f;
    }
    __syncthreads();
    const int vbzero = *reinterpret_cast<const int*>(sm + OFF_FLAG);

    // thread decompositions (constant per thread)
    // stage 1: 4m x 4n per thread
    const int s1_wid = tid >> 5, s1_lane = tid & 31;
    const int s1_wm = s1_wid & 3, s1_wn = s1_wid >> 2;
    const int s1_ng = s1_lane & 7, s1_mg = s1_lane >> 3;
    const int s1_mrow = s1_wm * 16 + s1_mg * 4;
    const int s1_n0   = s1_wn * 32 + s1_ng * 4;
    const unsigned s1_gbase = smb + (unsigned)(OFF_G * 4) + s1_mrow * (PITCH * 4);
    const unsigned s1_wbase = smb + (unsigned)(OFF_OW1 * 4) + s1_n0 * 8;
    // stage 2: 1m x 8h x (k/2) per thread
    const int s2_lane = tid & 31;
    const int s2_mw = (tid >> 5) & 1;
    const int s2_ht = (tid >> 6) & 3;
    const int s2_ks = tid >> 8;
    const int s2_m  = s2_mw * 32 + s2_lane;
    const int s2_h0 = s2_ht * 8;
    // gaussian stage: 4 chunks of (m, k4)
    const int gk4 = (tid & 31) * 4;
    const int gmw = tid >> 5;   // + itc*16

    for (int t = blockIdx.x; t < NTILES; t += gridDim.x) {
        int b, rowi, j0, isLP;
        if (t < NT_LL) {
            isLP = 0;
            b = t >> 10;
            int r = t & 1023;
            rowi = r >> 2;
            j0 = (r & 3) << 6;
        } else {
            isLP = 1;
            int u = t - NT_LL;
            b = u / 3072;
            int r = u % 3072;
            rowi = LLEN + (r >> 2);
            j0 = (r & 3) << 6;
        }

        // ---- Edge metadata ----
        if (tid < TM) {
            int j = j0 + tid;
            const float* pj = pos + ((size_t)b * NTOT + j) * 3;
            const float* pi = pos + ((size_t)b * NTOT + rowi) * 3;
            float d0 = pj[0] - pi[0];
            float d1 = pj[1] - pi[1];
            float d2 = pj[2] - pi[2];
            float d = 1.0f / (d0 * d0 + d1 * d1 + d2 * d2 + 1.0f);
            int e = etype[((size_t)b * NTOT + rowi) * NTOT + j];
            sm[OFF_X0 + tid] = mw[e] * d + bw[e];
            sm[OFF_DLM + tid * 3 + 0] = d0;
            sm[OFF_DLM + tid * 3 + 1] = d1;
            sm[OFF_DLM + tid * 3 + 2] = d2;
        }
        __syncthreads();   // (1)

        // ---- Gaussian features + vector-MLP hidden (vectorized over k4) ----
        #pragma unroll
        for (int itc = 0; itc < 4; itc++) {
            const int m = itc * 16 + gmw;
            const float x0 = sm[OFF_X0 + m];
            const float d0 = sm[OFF_DLM + m * 3 + 0];
            const float d1 = sm[OFF_DLM + m * 3 + 1];
            const float d2 = sm[OFF_DLM + m * 3 + 2];
            float4 mn = *reinterpret_cast<float4*>(sm + OFF_MEAN + gk4);
            float4 is = *reinterpret_cast<float4*>(sm + OFF_ISTD + gk4);
            float4 cf = *reinterpret_cast<float4*>(sm + OFF_COEF + gk4);
            float4 wa = *reinterpret_cast<float4*>(sm + OFF_VW1 + gk4);
            float4 wb = *reinterpret_cast<float4*>(sm + OFF_VW1 + KDIM + gk4);
            float4 wc = *reinterpret_cast<float4*>(sm + OFF_VW1 + 2 * KDIM + gk4);
            float4 vb = *reinterpret_cast<float4*>(sm + OFF_VB1 + gk4);
            float4 g, v1, v2, s;
            {
                float t0 = (x0 - mn.x) * is.x; g.x = __expf(-0.5f * t0 * t0) * cf.x;
                float t1 = (x0 - mn.y) * is.y; g.y = __expf(-0.5f * t1 * t1) * cf.y;
                float t2 = (x0 - mn.z) * is.z; g.z = __expf(-0.5f * t2 * t2) * cf.z;
                float t3 = (x0 - mn.w) * is.w; g.w = __expf(-0.5f * t3 * t3) * cf.w;
            }
            s.x = d0 * wa.x + d1 * wb.x + d2 * wc.x + vb.x;
            s.y = d0 * wa.y + d1 * wb.y + d2 * wc.y + vb.y;
            s.z = d0 * wa.z + d1 * wb.z + d2 * wc.z + vb.z;
            s.w = d0 * wa.w + d1 * wb.w + d2 * wc.w + vb.w;
            v1.x = gelu_exact(s.x); v1.y = gelu_exact(s.y);
            v1.z = gelu_exact(s.z); v1.w = gelu_exact(s.w);
            *reinterpret_cast<float4*>(sm + OFF_G  + m * PITCH + gk4) = g;
            *reinterpret_cast<float4*>(sm + OFF_V1 + m * PITCH + gk4) = v1;
            if (isLP) {
                if (vbzero) {
                    v2.x = v1.x - s.x; v2.y = v1.y - s.y;
                    v2.z = v1.z - s.z; v2.w = v1.w - s.w;
                } else {
                    v2.x = gelu_exact(2.0f * vb.x - s.x);
                    v2.y = gelu_exact(2.0f * vb.y - s.y);
                    v2.z = gelu_exact(2.0f * vb.z - s.z);
                    v2.w = gelu_exact(2.0f * vb.w - s.w);
                }
                *reinterpret_cast<float4*>(sm + OFF_V2 + m * PITCH + gk4) = v2;
            }
        }
        __syncthreads();   // (2)

        // ---- Stage 1: H1 = gelu(G[64,128] @ ow1 + ob1); 4m x 4n x f32x2 ----
        {
            ull acc[4][4];
            #pragma unroll
            for (int r = 0; r < 4; r++)
                #pragma unroll
                for (int c = 0; c < 4; c++) acc[r][c] = 0ull;

            #pragma unroll 2
            for (int kp2 = 0; kp2 < 32; kp2++) {   // 2 k-pairs per iter
                ull ga[4], gb[4];
                #pragma unroll
                for (int r = 0; r < 4; r++)
                    lds_b128(ga[r], gb[r], s1_gbase + r * (PITCH * 4) + kp2 * 16);
                #pragma unroll
                for (int sub = 0; sub < 2; sub++) {
                    const unsigned wk = s1_wbase + (2 * kp2 + sub) * 1024;
                    ull w0, w1, w2_, w3;
                    lds_b128(w0, w1, wk);
                    lds_b128(w2_, w3, wk + 16);
                    #pragma unroll
                    for (int r = 0; r < 4; r++) {
                        ull g = sub ? gb[r] : ga[r];
                        acc[r][0] = ffma2(g, w0,  acc[r][0]);
                        acc[r][1] = ffma2(g, w1,  acc[r][1]);
                        acc[r][2] = ffma2(g, w2_, acc[r][2]);
                        acc[r][3] = ffma2(g, w3,  acc[r][3]);
                    }
                }
            }
            __syncthreads();   // (3) all G reads done before H1 overwrite
            float4 ob = *reinterpret_cast<float4*>(sm + OFF_OB1 + s1_n0);
            #pragma unroll
            for (int r = 0; r < 4; r++) {
                float2 a0 = u2f2(acc[r][0]), a1 = u2f2(acc[r][1]);
                float2 a2 = u2f2(acc[r][2]), a3 = u2f2(acc[r][3]);
                float4 o;
                o.x = gelu_exact(a0.x + a0.y + ob.x);
                o.y = gelu_exact(a1.x + a1.y + ob.y);
                o.z = gelu_exact(a2.x + a2.y + ob.z);
                o.w = gelu_exact(a3.x + a3.y + ob.w);
                *reinterpret_cast<float4*>(sm + OFF_G + (s1_mrow + r) * PITCH + s1_n0) = o;
            }
        }
        __syncthreads();   // (4)

        // ---- Stage 2: 1m x 8h, k-split 2, f32x2; partial-sum reduce via scratch ----
        {
            const unsigned gA  = smb + (unsigned)(OFF_G  * 4) + s2_m * (PITCH * 4) + s2_ks * 256;
            const unsigned pA  = smb + (unsigned)(OFF_V1 * 4) + s2_m * (PITCH * 4) + s2_ks * 256;
            const unsigned qA  = smb + (unsigned)(OFF_V2 * 4) + s2_m * (PITCH * 4) + s2_ks * 256;
            const unsigned woA = smb + (unsigned)(OFF_OW2 * 4) + s2_ks * 8192 + s2_h0 * 8;
            const unsigned wvA = smb + (unsigned)(OFF_VW2 * 4) + s2_ks * 8192 + s2_h0 * 8;
            ull E[8], A[8], C[8];
            #pragma unroll
            for (int j = 0; j < 8; j++) { E[j] = 0ull; A[j] = 0ull; C[j] = 0ull; }

            if (!isLP) {
                for (int it = 0; it < 16; it++) {
                    ull gx, gy, px, py;
                    lds_b128(gx, gy, gA + it * 16);
                    lds_b128(px, py, pA + it * 16);
                    #pragma unroll
                    for (int sub = 0; sub < 2; sub++) {
                        const unsigned ko = it * 512 + sub * 256;
                        ull g = sub ? gy : gx;
                        ull p = sub ? py : px;
                        #pragma unroll
                        for (int gr = 0; gr < 4; gr++) {
                            ull wa, wb;
                            lds_b128(wa, wb, woA + ko + gr * 16);
                            E[2*gr]   = ffma2(g, wa, E[2*gr]);
                            E[2*gr+1] = ffma2(g, wb, E[2*gr+1]);
                            ull va, vbw;
                            lds_b128(va, vbw, wvA + ko + gr * 16);
                            A[2*gr]   = ffma2(p, va,  A[2*gr]);
                            A[2*gr+1] = ffma2(p, vbw, A[2*gr+1]);
                        }
                    }
                }
            } else {
                for (int it = 0; it < 16; it++) {
                    ull gx, gy, px, py, qx, qy;
                    lds_b128(gx, gy, gA + it * 16);
                    lds_b128(px, py, pA + it * 16);
                    lds_b128(qx, qy, qA + it * 16);
                    #pragma unroll
                    for (int sub = 0; sub < 2; sub++) {
                        const unsigned ko = it * 512 + sub * 256;
                        ull g = sub ? gy : gx;
                        ull p = sub ? py : px;
                        ull q = sub ? qy : qx;
                        #pragma unroll
                        for (int gr = 0; gr < 4; gr++) {
                            ull wa, wb;
                            lds_b128(wa, wb, woA + ko + gr * 16);
                            E[2*gr]   = ffma2(g, wa, E[2*gr]);
                            E[2*gr+1] = ffma2(g, wb, E[2*gr+1]);
                            ull va, vbw;
                            lds_b128(va, vbw, wvA + ko + gr * 16);
                            A[2*gr]   = ffma2(p, va,  A[2*gr]);
                            A[2*gr+1] = ffma2(p, vbw, A[2*gr+1]);
                            C[2*gr]   = ffma2(q, va,  C[2*gr]);
                            C[2*gr+1] = ffma2(q, vbw, C[2*gr+1]);
                        }
                    }
                }
            }

            // per-thread combine: rowv = ef + va, colv = ef + vc
            float rowv[8], colv[8];
            #pragma unroll
            for (int j = 0; j < 8; j++) {
                float2 e = u2f2(E[j]);
                float2 a = u2f2(A[j]);
                float ev = e.x + e.y;
                rowv[j] = ev + a.x + a.y;
                if (isLP) { float2 c = u2f2(C[j]); colv[j] = ev + c.x + c.y; }
            }

            float* scr = sm + OFF_SCR + s2_m * SCPITCH + s2_h0;
            if (s2_ks == 1) {
                *reinterpret_cast<float4*>(scr)     = make_float4(rowv[0], rowv[1], rowv[2], rowv[3]);
                *reinterpret_cast<float4*>(scr + 4) = make_float4(rowv[4], rowv[5], rowv[6], rowv[7]);
                if (isLP) {
                    *reinterpret_cast<float4*>(scr + 32)     = make_float4(colv[0], colv[1], colv[2], colv[3]);
                    *reinterpret_cast<float4*>(scr + 36)     = make_float4(colv[4], colv[5], colv[6], colv[7]);
                }
            }
            __syncthreads();   // (5)
            if (s2_ks == 0) {
                float4 r0 = *reinterpret_cast<float4*>(scr);
                float4 r1 = *reinterpret_cast<float4*>(scr + 4);
                rowv[0] += r0.x; rowv[1] += r0.y; rowv[2] += r0.z; rowv[3] += r0.w;
                rowv[4] += r1.x; rowv[5] += r1.y; rowv[6] += r1.z; rowv[7] += r1.w;
                if (isLP) {
                    float4 c0 = *reinterpret_cast<float4*>(scr + 32);
                    float4 c1 = *reinterpret_cast<float4*>(scr + 36);
                    colv[0] += c0.x; colv[1] += c0.y; colv[2] += c0.z; colv[3] += c0.w;
                    colv[4] += c1.x; colv[5] += c1.y; colv[6] += c1.z; colv[7] += c1.w;
                }
                const size_t bh = (size_t)b * HDIM;
                #pragma unroll
                for (int j = 0; j < 8; j++) {
                    int h = s2_h0 + j;
                    float bb = sm[OFF_B2 + h];
                    size_t rb = ((bh + h) * NTOT + rowi) * NTOT + j0 + s2_m;
                    out[rb] = rowv[j] + bb;
                    if (isLP) {
                        size_t cb = ((bh + h) * NTOT + (j0 + s2_m)) * NTOT + rowi;
                        out[cb] = colv[j] + bb;
                    }
                }
            }
        }
        // next-iteration sync (1) orders buffer reuse for X0/DLM;
        // G/V1/V2 overwrite is ordered by sync (5) + sync (2).
    }
}

extern "C" void kernel_launch(void* const* d_in, const int* in_sizes, int n_in,
                              void* d_out, int out_size) {
    const float* pos    = (const float*)d_in[0];
    const int*   etype  = (const int*)d_in[1];
    const float* means  = (const float*)d_in[3];
    const float* stds   = (const float*)d_in[4];
    const float* mul_w  = (const float*)d_in[5];
    const float* bias_w = (const float*)d_in[6];
    const float* ow1    = (const float*)d_in[7];
    const float* ob1    = (const float*)d_in[8];
    const float* ow2    = (const float*)d_in[9];
    const float* ob2    = (const float*)d_in[10];
    const float* vw1    = (const float*)d_in[11];
    const float* vb1    = (const float*)d_in[12];
    const float* vw2    = (const float*)d_in[13];
    const float* vb2    = (const float*)d_in[14];
    float* out = (float*)d_out;

    cudaFuncSetAttribute(fused_distbias_kernel,
                         cudaFuncAttributeMaxDynamicSharedMemorySize, SMEM_BYTES);

    {
        size_t total = (size_t)BDIM * HDIM * PLEN * (PLEN / 4);
        int grid = (int)((total + 255) / 256);
        zero_pp_kernel<<<grid, 256>>>(out);
    }

    fused_distbias_kernel<<<148, 512, SMEM_BYTES>>>(
        pos, etype, mul_w, bias_w, means, stds,
        ow1, ob1, ow2, ob2, vw1, vb1, vw2, vb2, out);
}

// round 5
// speedup vs baseline: 1.2222x; 1.2222x over previous
#include <cuda_runtime.h>
#include <math.h>

// Problem dims (fixed by setup_inputs)
#define BDIM 2
#define NTOT 1024
#define PLEN 768
#define LLEN 256
#define KDIM 128
#define HDIM 32

constexpr int TM    = 64;
constexpr int PP    = 132;   // pair-major row pitch in floats (64 float2 + pad), 528B
constexpr int NT_LL = BDIM * LLEN * (LLEN / TM);   // 2048
constexpr int NT_LP = BDIM * PLEN * (LLEN / TM);   // 6144
constexpr int NTILES = NT_LL + NT_LP;              // 8192

// shared memory layout (float offsets)
// OW1P[kp][2c+{0,1}] = {ow1[2kp][c], ow1[2kp+1][c]}          (64 x 256 floats)
// OW2P/VW2P[kp][2h+{0,1}] = {w[2kp][h], w[2kp+1][h]}          (64 x 64 floats)
// GP/VP1[kp][2m+{0,1}] = {x[m][2kp], x[m][2kp+1]}, pitch PP   (GP reused as H1 pair-major)
constexpr int OFF_OW1  = 0;                         // 16384
constexpr int OFF_OW2  = 16384;                     // 4096
constexpr int OFF_VW2  = 20480;                     // 4096
constexpr int OFF_TVV  = 24576;                     // 96   T[d][h] = vw1 @ vw2
constexpr int OFF_VW1  = 24672;                     // 384
constexpr int OFF_VB1  = 25056;                     // 128
constexpr int OFF_OB1  = 25184;                     // 128
constexpr int OFF_MEAN = 25312;                     // 128
constexpr int OFF_ISTD = 25440;                     // 128
constexpr int OFF_COEF = 25568;                     // 128
constexpr int OFF_B2   = 25696;                     // 32
constexpr int OFF_FLAG = 25728;                     // 4
constexpr int OFF_DLM4 = 25732;                     // 256  DLM4[m] = {d0,d1,d2,x0}
constexpr int OFF_GP   = 25988;                     // 64*PP = 8448
constexpr int OFF_VP1  = OFF_GP + 64 * PP;          // 34436
constexpr int OFF_SCR1 = OFF_VP1 + 64 * PP;         // 42884  [64][33]
constexpr int OFF_SCR2 = OFF_SCR1 + 64 * 33;        // 44996  [64][33]
constexpr int SMEM_FLOATS = OFF_SCR2 + 64 * 33;     // 47108
constexpr int SMEM_BYTES  = SMEM_FLOATS * 4;        // 188432

typedef unsigned long long ull;

__device__ __forceinline__ ull ffma2(ull a, ull b, ull c) {
    ull d; asm("fma.rn.f32x2 %0,%1,%2,%3;" : "=l"(d) : "l"(a), "l"(b), "l"(c)); return d;
}
__device__ __forceinline__ float2 u2f2(ull v) {
    float2 f; asm("mov.b64 {%0,%1},%2;" : "=f"(f.x), "=f"(f.y) : "l"(v)); return f;
}
__device__ __forceinline__ ull f2pack(float x, float y) {
    ull r; asm("mov.b64 %0,{%1,%2};" : "=l"(r) : "f"(x), "f"(y)); return r;
}
__device__ __forceinline__ float gelu_exact(float x) {
    return 0.5f * x * (1.0f + erff(x * 0.70710678118654752f));
}

// Zero-fill the protein-protein quadrant: out[b,h,i>=L,j>=L]
__global__ void zero_pp_kernel(float* __restrict__ out) {
    const int q = PLEN / 4;
    size_t idx = (size_t)blockIdx.x * blockDim.x + threadIdx.x;
    size_t total = (size_t)BDIM * HDIM * PLEN * q;
    if (idx >= total) return;
    int jq = (int)(idx % q);
    size_t r = idx / q;
    int ip = (int)(r % PLEN);
    size_t bh = r / PLEN;
    size_t addr = (bh * NTOT + (LLEN + ip)) * NTOT + LLEN + 4 * jq;
    *reinterpret_cast<float4*>(out + addr) = make_float4(0.f, 0.f, 0.f, 0.f);
}

__global__ __launch_bounds__(512, 1)
void fused_distbias_kernel(
    const float* __restrict__ pos,
    const int*   __restrict__ etype,
    const float* __restrict__ mw,
    const float* __restrict__ bw,
    const float* __restrict__ means,
    const float* __restrict__ stds,
    const float* __restrict__ ow1,
    const float* __restrict__ ob1,
    const float* __restrict__ ow2,
    const float* __restrict__ ob2,
    const float* __restrict__ vw1,
    const float* __restrict__ vb1,
    const float* __restrict__ vw2,
    const float* __restrict__ vb2,
    float* __restrict__ out)
{
    extern __shared__ float sm[];
    const int tid = threadIdx.x;

    // ---- Stage weights (pair-major), once per block ----
    for (int i = tid; i < 64 * 128; i += 512) {
        int kp = i >> 7, c = i & 127;
        sm[OFF_OW1 + kp * 256 + 2 * c]     = ow1[(2 * kp) * KDIM + c];
        sm[OFF_OW1 + kp * 256 + 2 * c + 1] = ow1[(2 * kp + 1) * KDIM + c];
    }
    for (int i = tid; i < 64 * 32; i += 512) {
        int kp = i >> 5, h = i & 31;
        sm[OFF_OW2 + kp * 64 + 2 * h]     = ow2[(2 * kp) * HDIM + h];
        sm[OFF_OW2 + kp * 64 + 2 * h + 1] = ow2[(2 * kp + 1) * HDIM + h];
        sm[OFF_VW2 + kp * 64 + 2 * h]     = vw2[(2 * kp) * HDIM + h];
        sm[OFF_VW2 + kp * 64 + 2 * h + 1] = vw2[(2 * kp + 1) * HDIM + h];
    }
    for (int i = tid; i < 3 * KDIM; i += 512) sm[OFF_VW1 + i] = vw1[i];
    for (int i = tid; i < KDIM; i += 512) {
        sm[OFF_VB1 + i] = vb1[i];
        sm[OFF_OB1 + i] = ob1[i];
        float s  = fabsf(stds[i]) + 1e-5f;
        float is = 1.0f / s;
        sm[OFF_MEAN + i] = means[i];
        sm[OFF_ISTD + i] = is;
        sm[OFF_COEF + i] = is * (1.0f / sqrtf(2.0f * 3.14159f));
    }
    if (tid < HDIM) sm[OFF_B2 + tid] = ob2[tid] + vb2[tid];
    if (tid == 0) {
        int f = 1;
        for (int k = 0; k < KDIM; k++) if (vb1[k] != 0.0f) { f = 0; break; }
        *reinterpret_cast<int*>(sm + OFF_FLAG) = f;
    }
    __syncthreads();
    // T[d][h] = sum_k vw1[d][k] * vw2[k][h]
    if (tid < 96) {
        int d = tid >> 5, h = tid & 31;
        float s = 0.0f;
        for (int kp = 0; kp < 64; kp++) {
            float2 a = *reinterpret_cast<float2*>(sm + OFF_VW1 + d * 128 + 2 * kp);
            float2 w = *reinterpret_cast<float2*>(sm + OFF_VW2 + kp * 64 + 2 * h);
            s += a.x * w.x + a.y * w.y;
        }
        sm[OFF_TVV + d * 32 + h] = s;
    }
    __syncthreads();
    const int vbzero = *reinterpret_cast<const int*>(sm + OFF_FLAG);

    // ---- per-thread decompositions ----
    // gaussian: m per lane, k-chunks per warp-group
    const int gm  = tid & 63;        // m
    const int gkc = tid >> 6;        // 8 kp per thread: kp = gkc*8 + i
    // stage 1: warp (wm, wn), lane (mg, ng); thread: 4m x cols {2ng,2ng+1,2ng+16,2ng+17}+cbase
    const int s1_wid = tid >> 5, s1_lane = tid & 31;
    const int s1_wm = s1_wid & 3, s1_wn = s1_wid >> 2;
    const int s1_mg = s1_lane >> 3, s1_ng = s1_lane & 7;
    const int s1_mbase = s1_wm * 16 + s1_mg * 4;
    const int s1_cbase = s1_wn * 32;
    const int s1_npA   = s1_wn * 16 + s1_ng;
    // stage 2: warp = hg(4) x kh(2) x mh(2); thread: 1 m, 8 h, 32 kp
    const int s2_hg = (tid >> 5) & 3;
    const int s2_kh = (tid >> 7) & 1;
    const int s2_mh = tid >> 8;
    const int s2_h0 = s2_hg * 8;
    const int s2_m  = s2_mh * 32 + (tid & 31);

    for (int t = blockIdx.x; t < NTILES; t += gridDim.x) {
        int b, rowi, j0, isLP;
        if (t < NT_LL) {
            isLP = 0;
            b = t >> 10;
            int r = t & 1023;
            rowi = r >> 2;
            j0 = (r & 3) << 6;
        } else {
            isLP = 1;
            int u = t - NT_LL;
            b = u / 3072;
            int r = u % 3072;
            rowi = LLEN + (r >> 2);
            j0 = (r & 3) << 6;
        }

        // ---- Edge metadata: DLM4[m] = {d0,d1,d2,x0} ----
        if (tid < TM) {
            int j = j0 + tid;
            const float* pj = pos + ((size_t)b * NTOT + j) * 3;
            const float* pi = pos + ((size_t)b * NTOT + rowi) * 3;
            float d0 = pj[0] - pi[0];
            float d1 = pj[1] - pi[1];
            float d2 = pj[2] - pi[2];
            float d = 1.0f / (d0 * d0 + d1 * d1 + d2 * d2 + 1.0f);
            int e = etype[((size_t)b * NTOT + rowi) * NTOT + j];
            float x0 = mw[e] * d + bw[e];
            *reinterpret_cast<float4*>(sm + OFF_DLM4 + tid * 4) =
                make_float4(d0, d1, d2, x0);
        }
        __syncthreads();   // (1)

        // ---- Gaussian features + vector-MLP hidden (pair-major stores) ----
        {
            float4 dm = *reinterpret_cast<float4*>(sm + OFF_DLM4 + gm * 4);
            #pragma unroll
            for (int i = 0; i < 8; i++) {
                int kp = gkc * 8 + i;
                float2 mn = *reinterpret_cast<float2*>(sm + OFF_MEAN + 2 * kp);
                float2 is = *reinterpret_cast<float2*>(sm + OFF_ISTD + 2 * kp);
                float2 cf = *reinterpret_cast<float2*>(sm + OFF_COEF + 2 * kp);
                float2 w0 = *reinterpret_cast<float2*>(sm + OFF_VW1 + 2 * kp);
                float2 w1 = *reinterpret_cast<float2*>(sm + OFF_VW1 + 128 + 2 * kp);
                float2 w2 = *reinterpret_cast<float2*>(sm + OFF_VW1 + 256 + 2 * kp);
                float2 vb = *reinterpret_cast<float2*>(sm + OFF_VB1 + 2 * kp);
                float tx = (dm.w - mn.x) * is.x;
                float ty = (dm.w - mn.y) * is.y;
                float2 g = make_float2(__expf(-0.5f * tx * tx) * cf.x,
                                       __expf(-0.5f * ty * ty) * cf.y);
                float sx = dm.x * w0.x + dm.y * w1.x + dm.z * w2.x + vb.x;
                float sy = dm.x * w0.y + dm.y * w1.y + dm.z * w2.y + vb.y;
                float2 v1 = make_float2(gelu_exact(sx), gelu_exact(sy));
                *reinterpret_cast<float2*>(sm + OFF_GP  + kp * PP + 2 * gm) = g;
                *reinterpret_cast<float2*>(sm + OFF_VP1 + kp * PP + 2 * gm) = v1;
            }
        }
        __syncthreads();   // (2)

        // ---- Stage 1: H1 = gelu(G @ ow1 + ob1); FFMA2, pair-major in & out ----
        ull acc[4][4];
        #pragma unroll
        for (int r = 0; r < 4; r++)
            #pragma unroll
            for (int j = 0; j < 4; j++) acc[r][j] = 0ull;
        {
            const float* gpB = sm + OFF_GP + 2 * s1_mbase;
            const float* w1B = sm + OFF_OW1 + 2 * s1_cbase + 4 * s1_ng;
            #pragma unroll 4
            for (int kp = 0; kp < 64; kp++) {
                ulonglong2 g01 = *reinterpret_cast<const ulonglong2*>(gpB + kp * PP);
                ulonglong2 g23 = *reinterpret_cast<const ulonglong2*>(gpB + kp * PP + 4);
                ulonglong2 wA  = *reinterpret_cast<const ulonglong2*>(w1B + kp * 256);
                ulonglong2 wB  = *reinterpret_cast<const ulonglong2*>(w1B + kp * 256 + 32);
                acc[0][0] = ffma2(g01.x, wA.x, acc[0][0]);
                acc[0][1] = ffma2(g01.x, wA.y, acc[0][1]);
                acc[0][2] = ffma2(g01.x, wB.x, acc[0][2]);
                acc[0][3] = ffma2(g01.x, wB.y, acc[0][3]);
                acc[1][0] = ffma2(g01.y, wA.x, acc[1][0]);
                acc[1][1] = ffma2(g01.y, wA.y, acc[1][1]);
                acc[1][2] = ffma2(g01.y, wB.x, acc[1][2]);
                acc[1][3] = ffma2(g01.y, wB.y, acc[1][3]);
                acc[2][0] = ffma2(g23.x, wA.x, acc[2][0]);
                acc[2][1] = ffma2(g23.x, wA.y, acc[2][1]);
                acc[2][2] = ffma2(g23.x, wB.x, acc[2][2]);
                acc[2][3] = ffma2(g23.x, wB.y, acc[2][3]);
                acc[3][0] = ffma2(g23.y, wA.x, acc[3][0]);
                acc[3][1] = ffma2(g23.y, wA.y, acc[3][1]);
                acc[3][2] = ffma2(g23.y, wB.x, acc[3][2]);
                acc[3][3] = ffma2(g23.y, wB.y, acc[3][3]);
            }
        }
        __syncthreads();   // (3) all GP reads done before H1 overwrite
        {
            float2 obA = *reinterpret_cast<float2*>(sm + OFF_OB1 + s1_cbase + 2 * s1_ng);
            float2 obB = *reinterpret_cast<float2*>(sm + OFF_OB1 + s1_cbase + 2 * s1_ng + 16);
            #pragma unroll
            for (int r = 0; r < 4; r++) {
                int m = s1_mbase + r;
                float2 a0 = u2f2(acc[r][0]), a1 = u2f2(acc[r][1]);
                float2 a2 = u2f2(acc[r][2]), a3 = u2f2(acc[r][3]);
                float2 hA = make_float2(gelu_exact(a0.x + a0.y + obA.x),
                                        gelu_exact(a1.x + a1.y + obA.y));
                float2 hB = make_float2(gelu_exact(a2.x + a2.y + obB.x),
                                        gelu_exact(a3.x + a3.y + obB.y));
                *reinterpret_cast<float2*>(sm + OFF_GP + s1_npA * PP + 2 * m) = hA;
                *reinterpret_cast<float2*>(sm + OFF_GP + (s1_npA + 8) * PP + 2 * m) = hB;
            }
        }
        __syncthreads();   // (4)

        // ---- Stage 2: ef/va contractions, k-split 2, pair-major streams ----
        {
            float4 dm = *reinterpret_cast<float4*>(sm + OFF_DLM4 + s2_m * 4);
            float corr[8];
            if (isLP) {
                #pragma unroll
                for (int j = 0; j < 8; j++) {
                    int h = s2_h0 + j;
                    corr[j] = dm.x * sm[OFF_TVV + h]
                            + dm.y * sm[OFF_TVV + 32 + h]
                            + dm.z * sm[OFF_TVV + 64 + h];
                }
            }
            ull E[8], A[8], C[8];
            #pragma unroll
            for (int j = 0; j < 8; j++) { E[j] = 0ull; A[j] = 0ull; C[j] = 0ull; }

            const float* hpB = sm + OFF_GP  + s2_kh * 32 * PP + 2 * s2_m;
            const float* vpB = sm + OFF_VP1 + s2_kh * 32 * PP + 2 * s2_m;
            const float* woB = sm + OFF_OW2 + s2_kh * 32 * 64 + 2 * s2_h0;
            const float* wvB = sm + OFF_VW2 + s2_kh * 32 * 64 + 2 * s2_h0;

            #pragma unroll 2
            for (int i = 0; i < 32; i++) {
                ull hp = *reinterpret_cast<const ull*>(hpB + i * PP);
                ull vp = *reinterpret_cast<const ull*>(vpB + i * PP);
                ulonglong2 wo01 = *reinterpret_cast<const ulonglong2*>(woB + i * 64);
                ulonglong2 wo23 = *reinterpret_cast<const ulonglong2*>(woB + i * 64 + 4);
                ulonglong2 wo45 = *reinterpret_cast<const ulonglong2*>(woB + i * 64 + 8);
                ulonglong2 wo67 = *reinterpret_cast<const ulonglong2*>(woB + i * 64 + 12);
                ulonglong2 wv01 = *reinterpret_cast<const ulonglong2*>(wvB + i * 64);
                ulonglong2 wv23 = *reinterpret_cast<const ulonglong2*>(wvB + i * 64 + 4);
                ulonglong2 wv45 = *reinterpret_cast<const ulonglong2*>(wvB + i * 64 + 8);
                ulonglong2 wv67 = *reinterpret_cast<const ulonglong2*>(wvB + i * 64 + 12);
                E[0] = ffma2(hp, wo01.x, E[0]); E[1] = ffma2(hp, wo01.y, E[1]);
                E[2] = ffma2(hp, wo23.x, E[2]); E[3] = ffma2(hp, wo23.y, E[3]);
                E[4] = ffma2(hp, wo45.x, E[4]); E[5] = ffma2(hp, wo45.y, E[5]);
                E[6] = ffma2(hp, wo67.x, E[6]); E[7] = ffma2(hp, wo67.y, E[7]);
                A[0] = ffma2(vp, wv01.x, A[0]); A[1] = ffma2(vp, wv01.y, A[1]);
                A[2] = ffma2(vp, wv23.x, A[2]); A[3] = ffma2(vp, wv23.y, A[3]);
                A[4] = ffma2(vp, wv45.x, A[4]); A[5] = ffma2(vp, wv45.y, A[5]);
                A[6] = ffma2(vp, wv67.x, A[6]); A[7] = ffma2(vp, wv67.y, A[7]);
                if (isLP && !vbzero) {   // correct fallback (not exercised: vb1==0)
                    int kp = s2_kh * 32 + i;
                    float2 w0 = *reinterpret_cast<float2*>(sm + OFF_VW1 + 2 * kp);
                    float2 w1 = *reinterpret_cast<float2*>(sm + OFF_VW1 + 128 + 2 * kp);
                    float2 w2 = *reinterpret_cast<float2*>(sm + OFF_VW1 + 256 + 2 * kp);
                    float2 vb = *reinterpret_cast<float2*>(sm + OFF_VB1 + 2 * kp);
                    float sx = dm.x * w0.x + dm.y * w1.x + dm.z * w2.x + vb.x;
                    float sy = dm.x * w0.y + dm.y * w1.y + dm.z * w2.y + vb.y;
                    ull q = f2pack(gelu_exact(2.0f * vb.x - sx),
                                   gelu_exact(2.0f * vb.y - sy));
                    C[0] = ffma2(q, wv01.x, C[0]); C[1] = ffma2(q, wv01.y, C[1]);
                    C[2] = ffma2(q, wv23.x, C[2]); C[3] = ffma2(q, wv23.y, C[3]);
                    C[4] = ffma2(q, wv45.x, C[4]); C[5] = ffma2(q, wv45.y, C[5]);
                    C[6] = ffma2(q, wv67.x, C[6]); C[7] = ffma2(q, wv67.y, C[7]);
                }
            }

            float rowp[8], amc[8];
            #pragma unroll
            for (int j = 0; j < 8; j++) {
                float2 e = u2f2(E[j]);
                float2 a = u2f2(A[j]);
                rowp[j] = e.x + e.y + a.x + a.y;
                if (isLP && !vbzero) {
                    float2 c = u2f2(C[j]);
                    amc[j] = (a.x + a.y) - (c.x + c.y);
                }
            }
            if (s2_kh == 1) {
                #pragma unroll
                for (int j = 0; j < 8; j++)
                    sm[OFF_SCR1 + s2_m * 33 + s2_h0 + j] = rowp[j];
                if (isLP && !vbzero)
                    #pragma unroll
                    for (int j = 0; j < 8; j++)
                        sm[OFF_SCR2 + s2_m * 33 + s2_h0 + j] = amc[j];
            }
            __syncthreads();   // (5)
            if (s2_kh == 0) {
                const size_t bh = (size_t)b * HDIM;
                #pragma unroll
                for (int j = 0; j < 8; j++) {
                    int h = s2_h0 + j;
                    float rs = rowp[j] + sm[OFF_SCR1 + s2_m * 33 + h];
                    float bb = sm[OFF_B2 + h];
                    size_t rb = ((bh + h) * NTOT + rowi) * NTOT + j0 + s2_m;
                    out[rb] = rs + bb;
                    if (isLP) {
                        float sub = vbzero ? corr[j]
                                  : (amc[j] + sm[OFF_SCR2 + s2_m * 33 + h]);
                        size_t cb = ((bh + h) * NTOT + (j0 + s2_m)) * NTOT + rowi;
                        out[cb] = rs - sub + bb;
                    }
                }
            }
        }
        // loop-around: metadata writes are ordered by barrier (5) (all DLM4/GP/VP1
        // reads complete before it) plus barriers (1)-(4) of the next iteration.
    }
}

extern "C" void kernel_launch(void* const* d_in, const int* in_sizes, int n_in,
                              void* d_out, int out_size) {
    const float* pos    = (const float*)d_in[0];
    const int*   etype  = (const int*)d_in[1];
    const float* means  = (const float*)d_in[3];
    const float* stds   = (const float*)d_in[4];
    const float* mul_w  = (const float*)d_in[5];
    const float* bias_w = (const float*)d_in[6];
    const float* ow1    = (const float*)d_in[7];
    const float* ob1    = (const float*)d_in[8];
    const float* ow2    = (const float*)d_in[9];
    const float* ob2    = (const float*)d_in[10];
    const float* vw1    = (const float*)d_in[11];
    const float* vb1    = (const float*)d_in[12];
    const float* vw2    = (const float*)d_in[13];
    const float* vb2    = (const float*)d_in[14];
    float* out = (float*)d_out;

    cudaFuncSetAttribute(fused_distbias_kernel,
                         cudaFuncAttributeMaxDynamicSharedMemorySize, SMEM_BYTES);

    {
        size_t total = (size_t)BDIM * HDIM * PLEN * (PLEN / 4);
        int grid = (int)((total + 255) / 256);
        zero_pp_kernel<<<grid, 256>>>(out);
    }

    fused_distbias_kernel<<<148, 512, SMEM_BYTES>>>(
        pos, etype, mul_w, bias_w, means, stds,
        ow1, ob1, ow2, ob2, vw1, vb1, vw2, vb2, out);
}